// round 16
// baseline (speedup 1.0000x reference)
#include <cuda_runtime.h>
#include <cstddef>
#include <cstdint>

#define NB 128  // batch

// ---------------- output layout (tuple concat, fp32) ----------------
static const size_t O_OUT   = 0;
static const size_t O_PENUL = 1280;
static const size_t O_L1B   = 1049856;
static const size_t O_L1R   = 5244160;
static const size_t O_L2B   = 9438464;
static const size_t O_L2R   = 17827072;
static const size_t O_L3B   = 26215680;
static const size_t O_L3R   = 28312832;
static const size_t O_L4B   = 30409984;
static const size_t O_L4R   = 34604288;
static const size_t O_L5B   = 38798592;
static const size_t O_L5R   = 39847168;

// ---------------- scratch ----------------
#define PLSZ 18939904
__device__ float    g_convB[16777216];
__device__ float    g_convR[16777216];
__device__ float    g_poolB[4194304];
__device__ float    g_poolR[4194304];
__device__ uint16_t g_pbin[2][PLSZ];
__device__ uint16_t g_prealH[2][PLSZ];
__device__ uint16_t g_prealL[2][PLSZ];
__device__ uint4    g_bwfB[571392];
__device__ uint4    g_bwfH[571392];
__device__ uint4    g_bwfL[571392];
__device__ double   g_part[16384];      // BN partials: [C<=512][16][2]

static const size_t FW1 = 0;
static const size_t FW2 = 18432;
static const size_t FW3 = 55296;
static const size_t FW4 = 129024;
static const size_t FW5 = 276480;

// ---------------- bf16 helpers ----------------
__device__ __forceinline__ uint16_t f2bf(float x) {
    uint16_t r; asm("cvt.rn.bf16.f32 %0, %1;" : "=h"(r) : "f"(x)); return r;
}
__device__ __forceinline__ float bf2f(uint16_t h) {
    return __uint_as_float(((uint32_t)h) << 16);
}

// ---------------- FUSED weight prep: sign -> fragments directly ----------------
// grid = Cout/2 blocks; grp -> (ocblk, w_, mt, gid); rows (oc, oc+8).
template<int CIN>
__global__ void __launch_bounds__(256) wsignF_k(const float* __restrict__ w,
                                                uint4* __restrict__ frag) {
    constexpr int K = CIN * 9;
    constexpr int NCH = K / 16;
    __shared__ float rows[2][K];
    __shared__ double shd[256];
    int tid = threadIdx.x;
    int grp = blockIdx.x;
    int ocblk = grp >> 6;
    int w_ = (grp >> 4) & 3, mt = (grp >> 3) & 1, gid = grp & 7;
    int oc_lo = ocblk * 128 + w_ * 32 + mt * 16 + gid;
    const float* wlo = w + (size_t)oc_lo * K;
    const float* whi = w + (size_t)(oc_lo + 8) * K;
    for (int j = tid; j < K; j += 256) { rows[0][j] = wlo[j]; rows[1][j] = whi[j]; }
    __syncthreads();
    int half = tid >> 7, t = tid & 127;
    double s = 0.0;
    for (int j = t; j < K; j += 128) s += (double)rows[half][j];
    shd[tid] = s; __syncthreads();
    for (int st = 64; st > 0; st >>= 1) {
        if (t < st) shd[tid] += shd[tid + st];
        __syncthreads();
    }
    float m_lo = (float)(shd[0]   / (double)K);
    float m_hi = (float)(shd[128] / (double)K);
    auto sgn = [](float v, float m) -> uint32_t {
        float d = v - m;
        return (d > 0.f) ? 0x3F80u : ((d < 0.f) ? 0xBF80u : 0u);
    };
    // K-order: cg(64-cin group) major, then tap, then cin; w row layout [cin][tap]
    auto src = [&](int h, int k) -> float {
        int cg = k / 576; int r = k % 576; int tap = r / 64; int cin = cg * 64 + (r % 64);
        return rows[h][cin * 9 + tap];
    };
    for (int e = tid; e < NCH * 4; e += 256) {
        int c = e >> 2, tig = e & 3;
        int k0 = c * 16 + tig * 2;
        uint4 v;
        v.x = sgn(src(0, k0), m_lo)     | (sgn(src(0, k0 + 1), m_lo) << 16);
        v.y = sgn(src(1, k0), m_hi)     | (sgn(src(1, k0 + 1), m_hi) << 16);
        v.z = sgn(src(0, k0 + 8), m_lo) | (sgn(src(0, k0 + 9), m_lo) << 16);
        v.w = sgn(src(1, k0 + 8), m_hi) | (sgn(src(1, k0 + 9), m_hi) << 16);
        frag[((size_t)(ocblk * NCH + c)) * 256 + w_ * 64 + mt * 32 + gid * 4 + tig] = v;
    }
}

// ---------------- FUSED weight prep: real hi/lo -> fragments directly ----------------
template<int CIN>
__global__ void __launch_bounds__(256) wrealF_k(const float* __restrict__ w,
                                                uint4* __restrict__ fragH,
                                                uint4* __restrict__ fragL) {
    constexpr int K = CIN * 9;
    constexpr int NCH = K / 16;
    __shared__ float rows[2][K];
    int tid = threadIdx.x;
    int grp = blockIdx.x;
    int ocblk = grp >> 6;
    int w_ = (grp >> 4) & 3, mt = (grp >> 3) & 1, gid = grp & 7;
    int oc_lo = ocblk * 128 + w_ * 32 + mt * 16 + gid;
    const float* wlo = w + (size_t)oc_lo * K;
    const float* whi = w + (size_t)(oc_lo + 8) * K;
    for (int j = tid; j < K; j += 256) { rows[0][j] = wlo[j]; rows[1][j] = whi[j]; }
    __syncthreads();
    auto src = [&](int h, int k) -> float {
        int cg = k / 576; int r = k % 576; int tap = r / 64; int cin = cg * 64 + (r % 64);
        return rows[h][cin * 9 + tap];
    };
    for (int e = tid; e < NCH * 4; e += 256) {
        int c = e >> 2, tig = e & 3;
        int k0 = c * 16 + tig * 2;
        float vals[8] = { src(0, k0), src(0, k0 + 1), src(1, k0), src(1, k0 + 1),
                          src(0, k0 + 8), src(0, k0 + 9), src(1, k0 + 8), src(1, k0 + 9) };
        uint16_t h8[8], l8[8];
#pragma unroll
        for (int q = 0; q < 8; q++) {
            h8[q] = f2bf(vals[q]);
            l8[q] = f2bf(vals[q] - bf2f(h8[q]));
        }
        size_t at = ((size_t)(ocblk * NCH + c)) * 256 + w_ * 64 + mt * 32 + gid * 4 + tig;
        uint4 vh, vl;
        vh.x = (uint32_t)h8[0] | ((uint32_t)h8[1] << 16);
        vh.y = (uint32_t)h8[2] | ((uint32_t)h8[3] << 16);
        vh.z = (uint32_t)h8[4] | ((uint32_t)h8[5] << 16);
        vh.w = (uint32_t)h8[6] | ((uint32_t)h8[7] << 16);
        vl.x = (uint32_t)l8[0] | ((uint32_t)l8[1] << 16);
        vl.y = (uint32_t)l8[2] | ((uint32_t)l8[3] << 16);
        vl.z = (uint32_t)l8[4] | ((uint32_t)l8[5] << 16);
        vl.w = (uint32_t)l8[6] | ((uint32_t)l8[7] << 16);
        fragH[at] = vh; fragL[at] = vl;
    }
}

// ---------------- border zero for padded planes ----------------
__global__ void border_k(uint16_t* __restrict__ a, uint16_t* __restrict__ b,
                         int H, int W, int C) {
    int S = 2 * (W + 2) * C + 2 * H * C;
    size_t i = (size_t)blockIdx.x * 256 + threadIdx.x;
    int n = (int)(i / S);
    if (n >= NB) return;
    int r = (int)(i % S);
    int T = (W + 2) * C;
    int prow, pcol, c;
    if (r < T)            { prow = 0;     pcol = r / C;          c = r % C; }
    else if (r < 2 * T)   { int r2 = r - T; prow = H + 1; pcol = r2 / C; c = r2 % C; }
    else {
        int r3 = r - 2 * T;
        if (r3 < H * C)   { prow = 1 + r3 / C; pcol = 0;     c = r3 % C; }
        else              { int r4 = r3 - H * C; prow = 1 + r4 / C; pcol = W + 1; c = r4 % C; }
    }
    size_t at = (((size_t)n * (H + 2) + prow) * (W + 2) + pcol) * C + c;
    a[at] = 0;
    if (b) b[at] = 0;
}

// ---------------- FUSED: conv0 + w1 sign frags + w1 real frags + L1 borders ----------------
// [0,4096): conv0; [4096,4160): w1 sign frags; [4160,12608): borders; [12608,12672): w1 real frags
__global__ void __launch_bounds__(256) conv0wsign_k(const float* __restrict__ x,
                                                    const float* __restrict__ w0,
                                                    float* __restrict__ out,
                                                    const float* __restrict__ w1,
                                                    uint4* __restrict__ wfragB,
                                                    uint4* __restrict__ wfragH,
                                                    uint4* __restrict__ wfragL,
                                                    uint16_t* __restrict__ pb0,
                                                    uint16_t* __restrict__ pH0,
                                                    uint16_t* __restrict__ pL0) {
    __shared__ float As[9][64];
    __shared__ float Bs[10][10];
    __shared__ double shd[256];
    __shared__ float wrows[2][1152];
    int tid = threadIdx.x;

    if (blockIdx.x >= 12608) {
        // w1 real fragments (CIN=128, K=1152, NCH=72)
        int grp = blockIdx.x - 12608;
        int w_ = (grp >> 4) & 3, mt = (grp >> 3) & 1, gid = grp & 7;
        int oc_lo = w_ * 32 + mt * 16 + gid;
        const int K = 1152, NCH = 72;
        const float* wlo = w1 + (size_t)oc_lo * K;
        const float* whi = w1 + (size_t)(oc_lo + 8) * K;
        for (int j = tid; j < K; j += 256) { wrows[0][j] = wlo[j]; wrows[1][j] = whi[j]; }
        __syncthreads();
        auto src = [&](int h, int k) -> float {
            int cg = k / 576; int r = k % 576; int tap = r / 64; int cin = cg * 64 + (r % 64);
            return wrows[h][cin * 9 + tap];
        };
        for (int e = tid; e < NCH * 4; e += 256) {
            int c = e >> 2, tig = e & 3;
            int k0 = c * 16 + tig * 2;
            float vals[8] = { src(0, k0), src(0, k0 + 1), src(1, k0), src(1, k0 + 1),
                              src(0, k0 + 8), src(0, k0 + 9), src(1, k0 + 8), src(1, k0 + 9) };
            uint16_t h8[8], l8[8];
#pragma unroll
            for (int q = 0; q < 8; q++) {
                h8[q] = f2bf(vals[q]);
                l8[q] = f2bf(vals[q] - bf2f(h8[q]));
            }
            size_t at = ((size_t)c) * 256 + w_ * 64 + mt * 32 + gid * 4 + tig;
            uint4 vh, vl;
            vh.x = (uint32_t)h8[0] | ((uint32_t)h8[1] << 16);
            vh.y = (uint32_t)h8[2] | ((uint32_t)h8[3] << 16);
            vh.z = (uint32_t)h8[4] | ((uint32_t)h8[5] << 16);
            vh.w = (uint32_t)h8[6] | ((uint32_t)h8[7] << 16);
            vl.x = (uint32_t)l8[0] | ((uint32_t)l8[1] << 16);
            vl.y = (uint32_t)l8[2] | ((uint32_t)l8[3] << 16);
            vl.z = (uint32_t)l8[4] | ((uint32_t)l8[5] << 16);
            vl.w = (uint32_t)l8[6] | ((uint32_t)l8[7] << 16);
            wfragH[at] = vh; wfragL[at] = vl;
        }
        return;
    }

    if (blockIdx.x >= 4160) {
        // border zero, L1 input planes: H=W=32, C=128
        const int H = 32, W = 32, C = 128;
        const int T = (W + 2) * C;
        const int S = 2 * T + 2 * H * C;
        size_t i = (size_t)(blockIdx.x - 4160) * 256 + tid;
        int n = (int)(i / S);
        if (n >= NB) return;
        int r = (int)(i % S);
        int prow, pcol, c;
        if (r < T)          { prow = 0;  pcol = r / C; c = r % C; }
        else if (r < 2 * T) { int r2 = r - T; prow = H + 1; pcol = r2 / C; c = r2 % C; }
        else {
            int r3 = r - 2 * T;
            if (r3 < H * C) { prow = 1 + r3 / C; pcol = 0; c = r3 % C; }
            else            { int r4 = r3 - H * C; prow = 1 + r4 / C; pcol = W + 1; c = r4 % C; }
        }
        size_t at = (((size_t)n * (H + 2) + prow) * (W + 2) + pcol) * C + c;
        pb0[at] = 0; pH0[at] = 0; pL0[at] = 0;
        return;
    }

    if (blockIdx.x >= 4096) {
        // w1 sign fragments
        int grp = blockIdx.x - 4096;
        int w_  = (grp >> 4) & 3;
        int mt  = (grp >> 3) & 1;
        int gid = grp & 7;
        int oc_lo = w_ * 32 + mt * 16 + gid;
        int oc_hi = oc_lo + 8;
        const int K = 1152;
        int half = tid >> 7;
        int t    = tid & 127;
        const float* wp = w1 + (size_t)(half ? oc_hi : oc_lo) * K;
        double s = 0.0;
        for (int i = t; i < K; i += 128) s += (double)wp[i];
        shd[tid] = s; __syncthreads();
        for (int st = 64; st > 0; st >>= 1) {
            if (t < st) shd[tid] += shd[tid + st];
            __syncthreads();
        }
        float m_lo = (float)(shd[0]   / (double)K);
        float m_hi = (float)(shd[128] / (double)K);
        const float* wlo = w1 + (size_t)oc_lo * K;
        const float* whi = w1 + (size_t)oc_hi * K;
        auto sgn = [](float v, float m) -> uint32_t {
            float d = v - m;
            return (d > 0.f) ? 0x3F80u : ((d < 0.f) ? 0xBF80u : 0u);
        };
        auto src = [](const float* p, int k) -> float {
            int cg = k / 576; int r = k % 576; int tap = r / 64; int cin = cg * 64 + (r % 64);
            return p[cin * 9 + tap];
        };
        for (int e = tid; e < 72 * 4; e += 256) {
            int c = e >> 2, tig = e & 3;
            int k0 = c * 16 + tig * 2;
            uint4 v;
            v.x = sgn(src(wlo, k0), m_lo)     | (sgn(src(wlo, k0 + 1), m_lo) << 16);
            v.y = sgn(src(whi, k0), m_hi)     | (sgn(src(whi, k0 + 1), m_hi) << 16);
            v.z = sgn(src(wlo, k0 + 8), m_lo) | (sgn(src(wlo, k0 + 9), m_lo) << 16);
            v.w = sgn(src(whi, k0 + 8), m_hi) | (sgn(src(whi, k0 + 9), m_hi) << 16);
            wfragB[((size_t)c * 4 + w_) * 64 + mt * 32 + gid * 4 + tig] = v;
        }
        return;
    }

    // conv0
    const int CIN = 3, HH = 32, Cout = 128;
    int bx = blockIdx.x;
    int tile = bx & 15;
    int ty0 = (tile / 4) * 8;
    int tx0 = (tile % 4) * 8;
    int oc0 = ((bx >> 4) & 1) * 64;
    int n   = bx >> 5;
    int pos_t = tid & 15;
    int oc_t  = tid >> 4;

    float acc[4][4];
#pragma unroll
    for (int j = 0; j < 4; j++)
#pragma unroll
        for (int i = 0; i < 4; i++) acc[j][i] = 0.f;

    const float* inN = x + (size_t)n * CIN * HH * HH;

    for (int cin = 0; cin < CIN; cin++) {
        for (int idx = tid; idx < 576; idx += 256) {
            int oc = idx / 9, tap = idx % 9;
            As[tap][oc] = w0[(((size_t)(oc0 + oc)) * CIN + cin) * 9 + tap];
        }
        if (tid < 100) {
            int r = tid / 10, c = tid % 10;
            int gy = ty0 + r - 1, gx = tx0 + c - 1;
            float v = 0.f;
            if (gy >= 0 && gy < HH && gx >= 0 && gx < HH)
                v = inN[(size_t)cin * HH * HH + gy * HH + gx];
            Bs[r][c] = v;
        }
        __syncthreads();
#pragma unroll
        for (int tap = 0; tap < 9; tap++) {
            int dy = tap / 3, dx = tap % 3;
            float4 wv = *(const float4*)&As[tap][oc_t * 4];
#pragma unroll
            for (int j = 0; j < 4; j++) {
                int p = pos_t + 16 * j;
                float bv = Bs[(p >> 3) + dy][(p & 7) + dx];
                acc[j][0] += bv * wv.x;
                acc[j][1] += bv * wv.y;
                acc[j][2] += bv * wv.z;
                acc[j][3] += bv * wv.w;
            }
        }
        __syncthreads();
    }

#pragma unroll
    for (int j = 0; j < 4; j++) {
        int p = pos_t + 16 * j;
        int oy = ty0 + (p >> 3), ox = tx0 + (p & 7);
#pragma unroll
        for (int i = 0; i < 4; i++) {
            int oc = oc0 + oc_t * 4 + i;
            out[(((size_t)n * Cout + oc) * HH + oy) * HH + ox] = acc[j][i];
        }
    }
}

// ---------------- bf16 MMA + ldmatrix ----------------
__device__ __forceinline__ void mma_bf16(float* d, const uint32_t* a, const uint32_t* b) {
    asm volatile(
        "mma.sync.aligned.m16n8k16.row.col.f32.bf16.bf16.f32 "
        "{%0,%1,%2,%3}, {%4,%5,%6,%7}, {%8,%9}, {%0,%1,%2,%3};\n"
        : "+f"(d[0]), "+f"(d[1]), "+f"(d[2]), "+f"(d[3])
        : "r"(a[0]), "r"(a[1]), "r"(a[2]), "r"(a[3]),
          "r"(b[0]), "r"(b[1]));
}
__device__ __forceinline__ void ldsm_x4(uint32_t& r0, uint32_t& r1, uint32_t& r2, uint32_t& r3,
                                        uint32_t addr) {
    asm volatile("ldmatrix.sync.aligned.m8n8.x4.shared.b16 {%0,%1,%2,%3}, [%4];"
                 : "=r"(r0), "=r"(r1), "=r"(r2), "=r"(r3) : "r"(addr));
}

// ---------------- implicit-GEMM conv v8 (UNCHANGED from round 14/15) ----------------
template<int CIN, int H, bool SPLIT, bool POOL>
__global__ void __launch_bounds__(128) convmma_k(const uint16_t* __restrict__ inH,
                                                 const uint16_t* __restrict__ inL,
                                                 const uint4* __restrict__ wfH,
                                                 const uint4* __restrict__ wfL,
                                                 float* __restrict__ out,
                                                 int Cout) {
    constexpr int Wd = H;
    constexpr int HW = H * H;
    constexpr int K  = CIN * 9;
    constexpr int NCH = K / 16;
    constexpr int LGHW = (HW == 1024) ? 10 : (HW == 256) ? 8 : 6;
    constexpr int LGW  = (H == 32) ? 5 : (H == 16) ? 4 : 3;
    constexpr int NS = SPLIT ? 2 : 1;
    constexpr int NROWS = 64 / Wd;
    constexpr int PADP  = (NROWS + 2) * (Wd + 2);
    constexpr int NGRP  = CIN / 64;

    __shared__ __align__(16) uint16_t Ts[NS][PADP * 72];

    int tid  = threadIdx.x;
    int lane = tid & 31;
    int warp = tid >> 5;
    int gid  = lane >> 2;
    int tig  = lane & 3;

    int col0 = blockIdx.x * 64;
    int oc0  = blockIdx.y * 128;
    int nimg = col0 >> LGHW;
    int y0   = (col0 & (HW - 1)) >> LGW;
    size_t gtile = (((size_t)nimg * (H + 2) + y0) * (Wd + 2)) * CIN;

    size_t abase = (size_t)(oc0 >> 7) * NCH * 256 + (size_t)warp * 64 + lane;

    int posb[4];
    {
        int sub = ((lane >> 4) & 1) * 8 + (lane & 7);
        int kh  = (lane >> 3) & 1;
#pragma unroll
        for (int p = 0; p < 4; p++) {
            int bp = p * 16 + sub;
            int ry = bp >> LGW;
            int xx = bp & (Wd - 1);
            posb[p] = ((ry + 1) * (Wd + 2) + xx + 1) * 144 + kh * 16;
        }
    }
    uint32_t tb[NS];
#pragma unroll
    for (int s = 0; s < NS; s++)
        tb[s] = (uint32_t)__cvta_generic_to_shared(&Ts[s][0]);

    float acc[2][8][4];
#pragma unroll
    for (int mt = 0; mt < 2; mt++)
#pragma unroll
        for (int nt = 0; nt < 8; nt++)
#pragma unroll
            for (int r = 0; r < 4; r++) acc[mt][nt][r] = 0.f;

    uint4 acurH[2], acurL[2], anxtH[2], anxtL[2];
    auto load_A = [&](int c, uint4* aH, uint4* aL) {
#pragma unroll
        for (int mt = 0; mt < 2; mt++) {
            aH[mt] = wfH[abase + (size_t)c * 256 + mt * 32];
            if (SPLIT) aL[mt] = wfL[abase + (size_t)c * 256 + mt * 32];
        }
    };

    load_A(0, acurH, acurL);
    int c = 0;

    for (int cg = 0; cg < NGRP; cg++) {
        for (int it = tid; it < PADP * 8; it += 128) {
            int row = it >> 3, o = it & 7;
            size_t gsrc = gtile + (size_t)row * CIN + cg * 64 + o * 8;
            *(uint4*)&Ts[0][row * 72 + o * 8] = *(const uint4*)(inH + gsrc);
            if (SPLIT)
                *(uint4*)&Ts[1][row * 72 + o * 8] = *(const uint4*)(inL + gsrc);
        }
        __syncthreads();

#pragma unroll 1
        for (int tap = 0; tap < 9; tap++) {
            int to = ((tap / 3 - 1) * (Wd + 2) + (tap % 3 - 1)) * 144;
#pragma unroll
            for (int j = 0; j < 4; j++) {
                bool more = (c + 1 < NCH);
                if (more) load_A(c + 1, anxtH, anxtL);

                uint32_t bf[NS][8][2];
#pragma unroll
                for (int s = 0; s < NS; s++)
#pragma unroll
                    for (int p = 0; p < 4; p++)
                        ldsm_x4(bf[s][2 * p][0], bf[s][2 * p][1],
                                bf[s][2 * p + 1][0], bf[s][2 * p + 1][1],
                                tb[s] + (uint32_t)(posb[p] + to + j * 32));
#pragma unroll
                for (int mt = 0; mt < 2; mt++)
#pragma unroll
                    for (int nt = 0; nt < 8; nt++) {
                        if (SPLIT) {
                            mma_bf16(acc[mt][nt], (const uint32_t*)&acurL[mt], bf[0][nt]);
                            mma_bf16(acc[mt][nt], (const uint32_t*)&acurH[mt], bf[1][nt]);
                        }
                        mma_bf16(acc[mt][nt], (const uint32_t*)&acurH[mt], bf[0][nt]);
                    }
                if (more) {
                    acurH[0] = anxtH[0]; acurH[1] = anxtH[1];
                    if (SPLIT) { acurL[0] = anxtL[0]; acurL[1] = anxtL[1]; }
                }
                c++;
            }
        }
        __syncthreads();
    }

    if (!POOL) {
#pragma unroll
        for (int mt = 0; mt < 2; mt++) {
#pragma unroll
            for (int nt = 0; nt < 8; nt++) {
                int cc = col0 + nt * 8 + 2 * tig;
                int n_ = cc >> LGHW;
                int pp = cc & (HW - 1);
#pragma unroll
                for (int h = 0; h < 2; h++) {
                    int m = oc0 + warp * 32 + mt * 16 + gid + 8 * h;
                    float2 v = make_float2(acc[mt][nt][2 * h], acc[mt][nt][2 * h + 1]);
                    *(float2*)&out[((size_t)n_ * Cout + m) * HW + pp] = v;
                }
            }
        }
    } else {
        constexpr int PST = H / 8;
        constexpr int HO = H / 2;
#pragma unroll
        for (int mt = 0; mt < 2; mt++) {
#pragma unroll
            for (int nt = 0; nt < 8; nt++) {
                if (((nt / PST) & 1) != 0) continue;
                int np = nt + PST;
                int cc = col0 + nt * 8 + 2 * tig;
                int n_ = cc >> LGHW;
                int pos_ = cc & (HW - 1);
                int oy = (pos_ >> LGW) >> 1;
                int ox = (pos_ & (Wd - 1)) >> 1;
#pragma unroll
                for (int h = 0; h < 2; h++) {
                    int m = oc0 + warp * 32 + mt * 16 + gid + 8 * h;
                    float v = fmaxf(fmaxf(acc[mt][nt][2 * h], acc[mt][nt][2 * h + 1]),
                                    fmaxf(acc[mt][np][2 * h], acc[mt][np][2 * h + 1]));
                    out[((size_t)n_ * Cout + m) * (HO * HO) + oy * HO + ox] = v;
                }
            }
        }
    }
}

// ---------------- BN partial sums (deterministic, 16-way) ----------------
__global__ void bnstats_part_k(const float* __restrict__ x, int C, int HW,
                               double* __restrict__ part) {
    int c = blockIdx.x;
    int s = blockIdx.y;
    int tid = threadIdx.x;
    double s1 = 0.0, s2 = 0.0;
    for (int n = s * 8; n < s * 8 + 8; n++) {
        const float* xp = x + ((size_t)n * C + c) * HW;
        for (int p = tid; p < HW; p += 256) {
            float v = xp[p];
            s1 += (double)v;
            s2 += (double)v * (double)v;
        }
    }
    __shared__ double sh1[256], sh2[256];
    sh1[tid] = s1; sh2[tid] = s2; __syncthreads();
    for (int st = 128; st > 0; st >>= 1) {
        if (tid < st) { sh1[tid] += sh1[tid + st]; sh2[tid] += sh2[tid + st]; }
        __syncthreads();
    }
    if (tid == 0) {
        part[((size_t)c * 16 + s) * 2 + 0] = sh1[0];
        part[((size_t)c * 16 + s) * 2 + 1] = sh2[0];
    }
}

// ---------------- BN apply + hardtanh + padded plane pack, INLINE finalize ----------------
template<bool BIN, bool REALP, bool WF32>
__global__ void bnht_pack_k(const float* __restrict__ x, float* __restrict__ y32,
                            uint16_t* __restrict__ pbin,
                            uint16_t* __restrict__ pH, uint16_t* __restrict__ pL,
                            const double* __restrict__ part,
                            const float* __restrict__ g, const float* __restrict__ bb,
                            int C, int HW, int lgW) {
    __shared__ float ts[32][33];
    __shared__ float smean[32], srstd[32];
    int tx = threadIdx.x & 31, ty = threadIdx.x >> 5;
    int p0 = blockIdx.x * 32, c0 = blockIdx.y * 32, n = blockIdx.z;
    int W = 1 << lgW;
    int H = HW >> lgW;
    if (threadIdx.x < 32) {
        int c = c0 + threadIdx.x;
        double s1 = 0.0, s2 = 0.0;
#pragma unroll
        for (int s = 0; s < 16; s++) {
            s1 += part[((size_t)c * 16 + s) * 2 + 0];
            s2 += part[((size_t)c * 16 + s) * 2 + 1];
        }
        double M = (double)NB * HW;
        double m = s1 / M;
        double var = s2 / M - m * m;
        smean[threadIdx.x] = (float)m;
        srstd[threadIdx.x] = (float)(1.0 / sqrt(var + 1e-5));
    }
    __syncthreads();
#pragma unroll
    for (int r = 0; r < 4; r++) {
        int cl = ty + r * 8;
        int c = c0 + cl;
        size_t idx = ((size_t)n * C + c) * HW + p0 + tx;
        float v = x[idx];
        v = (v - smean[cl]) * srstd[cl] * g[c] + bb[c];
        v = fminf(1.f, fmaxf(-1.f, v));
        if (WF32) y32[idx] = v;
        ts[cl][tx] = v;
    }
    __syncthreads();
#pragma unroll
    for (int r = 0; r < 4; r++) {
        int p = p0 + ty + r * 8;
        int c = c0 + tx;
        float v = ts[tx][ty + r * 8];
        int py = p >> lgW, px = p & (W - 1);
        size_t a = (((size_t)n * (H + 2) + py + 1) * (W + 2) + px + 1) * C + c;
        if (BIN)
            pbin[a] = (v > 0.f) ? 0x3F80 : ((v < 0.f) ? 0xBF80 : 0);
        if (REALP) {
            uint16_t hi = f2bf(v);
            float lo = v - bf2f(hi);
            pH[a] = hi;
            pL[a] = f2bf(lo);
        }
    }
}

// ---------------- BN apply + hardtanh for L5 outputs (HW=16, C=512), inline finalize ----------------
__global__ void bnhtfin_k(const float* __restrict__ x, float* __restrict__ y,
                          const double* __restrict__ part,
                          const float* __restrict__ g, const float* __restrict__ bb) {
    __shared__ float smean[16], srstd[16];
    int tid = threadIdx.x;
    size_t base = (size_t)blockIdx.x * 256;
    int cbase = (int)((base >> 4) & 511);
    if (tid < 16) {
        int c = cbase + tid;
        double s1 = 0.0, s2 = 0.0;
#pragma unroll
        for (int s = 0; s < 16; s++) {
            s1 += part[((size_t)c * 16 + s) * 2 + 0];
            s2 += part[((size_t)c * 16 + s) * 2 + 1];
        }
        double M = (double)NB * 16;
        double m = s1 / M;
        double var = s2 / M - m * m;
        smean[tid] = (float)m;
        srstd[tid] = (float)(1.0 / sqrt(var + 1e-5));
    }
    __syncthreads();
    size_t i = base + tid;
    int cl = tid >> 4;
    int c = cbase + cl;
    float v = (x[i] - smean[cl]) * srstd[cl] * g[c] + bb[c];
    y[i] = fminf(1.f, fmaxf(-1.f, v));
}

// ---------------- copy ----------------
__global__ void copy_k(const float* __restrict__ src, float* __restrict__ dst) {
    size_t i = (size_t)blockIdx.x * 256 + threadIdx.x;
    dst[i] = src[i];
}

// ---------------- FC ----------------
__global__ void fc_k(const float* __restrict__ p, const float* __restrict__ w,
                     const float* __restrict__ b, float* __restrict__ out) {
    int n = blockIdx.x;
    int tid = threadIdx.x;
    float acc[10];
#pragma unroll
    for (int j = 0; j < 10; j++) acc[j] = 0.f;
    const float* pn = p + (size_t)n * 8192;
    for (int k = tid; k < 8192; k += 256) {
        float pv = pn[k];
#pragma unroll
        for (int j = 0; j < 10; j++) acc[j] += pv * w[(size_t)j * 8192 + k];
    }
    __shared__ float sh[256];
    for (int j = 0; j < 10; j++) {
        sh[tid] = acc[j]; __syncthreads();
        for (int st = 128; st > 0; st >>= 1) {
            if (tid < st) sh[tid] += sh[tid + st];
            __syncthreads();
        }
        if (tid == 0) out[n * 10 + j] = sh[0] + b[j];
        __syncthreads();
    }
}

// ---------------- host launch ----------------
extern "C" void kernel_launch(void* const* d_in, const int* in_sizes, int n_in,
                              void* d_out, int out_size) {
    (void)in_sizes; (void)n_in; (void)out_size;
    const float* x   = (const float*)d_in[0];
    const float* w0  = (const float*)d_in[1];
    const float* w1  = (const float*)d_in[2];
    const float* w2  = (const float*)d_in[3];
    const float* w3  = (const float*)d_in[4];
    const float* w4  = (const float*)d_in[5];
    const float* w5  = (const float*)d_in[6];
    const float* fcw = (const float*)d_in[7];
    const float* fcb = (const float*)d_in[8];
    const float* G[6], *B[6];
    for (int i = 0; i < 6; i++) { G[i] = (const float*)d_in[9 + 2*i]; B[i] = (const float*)d_in[10 + 2*i]; }
    float* out = (float*)d_out;

    float *convB, *convR, *poolB, *poolR;
    double *part;
    uint16_t *pbin, *prH, *prL;
    uint4 *bwfB, *bwfH, *bwfL;
    cudaGetSymbolAddress((void**)&convB, g_convB);
    cudaGetSymbolAddress((void**)&convR, g_convR);
    cudaGetSymbolAddress((void**)&poolB, g_poolB);
    cudaGetSymbolAddress((void**)&poolR, g_poolR);
    cudaGetSymbolAddress((void**)&pbin,  g_pbin);
    cudaGetSymbolAddress((void**)&prH,   g_prealH);
    cudaGetSymbolAddress((void**)&prL,   g_prealL);
    cudaGetSymbolAddress((void**)&bwfB,  g_bwfB);
    cudaGetSymbolAddress((void**)&bwfH,  g_bwfH);
    cudaGetSymbolAddress((void**)&bwfL,  g_bwfL);
    cudaGetSymbolAddress((void**)&part,  g_part);
    uint16_t* pb[2]  = { pbin, pbin + PLSZ };
    uint16_t* pH[2]  = { prH,  prH  + PLSZ };
    uint16_t* pL[2]  = { prL,  prL  + PLSZ };

    // 0: conv0 + w1 sign frags + w1 real frags + L1 borders
    conv0wsign_k<<<12672, 256>>>(x, w0, convB, w1, bwfB + FW1, bwfH + FW1, bwfL + FW1,
                                 pb[0], pH[0], pL[0]);
    // 1: BN partials for conv0 output
    bnstats_part_k<<<dim3(128, 16), 256>>>(convB, 128, 1024, part);
    // 2: BN apply + pack (inline finalize)
    bnht_pack_k<true, true, false><<<dim3(32, 4, NB), 256>>>(
        convB, nullptr, pb[0], pH[0], pL[0], part, G[0], B[0], 128, 1024, 5);
    // 3: REAL conv L1 <- PROFILED
    convmma_k<128, 32, true, true><<<dim3(2048, 1), 128>>>(
        pH[0], pL[0], bwfH + FW1, bwfL + FW1, poolR, 128);
    // 4: binary conv L1
    convmma_k<128, 32, false, true><<<dim3(2048, 1), 128>>>(
        pb[0], nullptr, bwfB + FW1, nullptr, poolB, 128);

    // weight prep for layers 2..5 (fused single-pass)
    wsignF_k<128><<<128, 256>>>(w2, bwfB + FW2);
    wrealF_k<128><<<128, 256>>>(w2, bwfH + FW2, bwfL + FW2);
    wsignF_k<256><<<128, 256>>>(w3, bwfB + FW3);
    wrealF_k<256><<<128, 256>>>(w3, bwfH + FW3, bwfL + FW3);
    wsignF_k<256><<<256, 256>>>(w4, bwfB + FW4);
    wrealF_k<256><<<256, 256>>>(w4, bwfH + FW4, bwfL + FW4);
    wsignF_k<512><<<256, 256>>>(w5, bwfB + FW5);
    wrealF_k<512><<<256, 256>>>(w5, bwfH + FW5, bwfL + FW5);

    // borders for L2-input planes (16,16,128)
    border_k<<<4353, 256>>>(pb[1], nullptr, 16, 16, 128);
    border_k<<<4353, 256>>>(pH[1], pL[1], 16, 16, 128);

    bnstats_part_k<<<dim3(128, 16), 256>>>(poolB, 128, 256, part);
    bnht_pack_k<true, false, true><<<dim3(8, 4, NB), 256>>>(
        poolB, out + O_L1B, pb[1], nullptr, nullptr, part, G[1], B[1], 128, 256, 4);
    bnstats_part_k<<<dim3(128, 16), 256>>>(poolR, 128, 256, part);
    bnht_pack_k<false, true, true><<<dim3(8, 4, NB), 256>>>(
        poolR, out + O_L1R, nullptr, pH[1], pL[1], part, G[1], B[1], 128, 256, 4);

    // Layer 2: 128->256 @16, no pool
    convmma_k<128, 16, false, false><<<dim3(512, 2), 128>>>(
        pb[1], nullptr, bwfB + FW2, nullptr, convB, 256);
    convmma_k<128, 16, true, false><<<dim3(512, 2), 128>>>(
        pH[1], pL[1], bwfH + FW2, bwfL + FW2, convR, 256);
    border_k<<<8704, 256>>>(pb[0], nullptr, 16, 16, 256);
    border_k<<<8704, 256>>>(pH[0], pL[0], 16, 16, 256);
    bnstats_part_k<<<dim3(256, 16), 256>>>(convB, 256, 256, part);
    bnht_pack_k<true, false, true><<<dim3(8, 8, NB), 256>>>(
        convB, out + O_L2B, pb[0], nullptr, nullptr, part, G[2], B[2], 256, 256, 4);
    bnstats_part_k<<<dim3(256, 16), 256>>>(convR, 256, 256, part);
    bnht_pack_k<false, true, true><<<dim3(8, 8, NB), 256>>>(
        convR, out + O_L2R, nullptr, pH[0], pL[0], part, G[2], B[2], 256, 256, 4);

    // Layer 3: 256->256 @16, fused pool -> 8
    convmma_k<256, 16, false, true><<<dim3(512, 2), 128>>>(
        pb[0], nullptr, bwfB + FW3, nullptr, poolB, 256);
    convmma_k<256, 16, true, true><<<dim3(512, 2), 128>>>(
        pH[0], pL[0], bwfH + FW3, bwfL + FW3, poolR, 256);
    border_k<<<4608, 256>>>(pb[1], nullptr, 8, 8, 256);
    border_k<<<4608, 256>>>(pH[1], pL[1], 8, 8, 256);
    bnstats_part_k<<<dim3(256, 16), 256>>>(poolB, 256, 64, part);
    bnht_pack_k<true, false, true><<<dim3(2, 8, NB), 256>>>(
        poolB, out + O_L3B, pb[1], nullptr, nullptr, part, G[3], B[3], 256, 64, 3);
    bnstats_part_k<<<dim3(256, 16), 256>>>(poolR, 256, 64, part);
    bnht_pack_k<false, true, true><<<dim3(2, 8, NB), 256>>>(
        poolR, out + O_L3R, nullptr, pH[1], pL[1], part, G[3], B[3], 256, 64, 3);

    // Layer 4: 256->512 @8, no pool
    convmma_k<256, 8, false, false><<<dim3(128, 4), 128>>>(
        pb[1], nullptr, bwfB + FW4, nullptr, convB, 512);
    convmma_k<256, 8, true, false><<<dim3(128, 4), 128>>>(
        pH[1], pL[1], bwfH + FW4, bwfL + FW4, convR, 512);
    border_k<<<9216, 256>>>(pb[0], nullptr, 8, 8, 512);
    border_k<<<9216, 256>>>(pH[0], pL[0], 8, 8, 512);
    bnstats_part_k<<<dim3(512, 16), 256>>>(convB, 512, 64, part);
    bnht_pack_k<true, false, true><<<dim3(2, 16, NB), 256>>>(
        convB, out + O_L4B, pb[0], nullptr, nullptr, part, G[4], B[4], 512, 64, 3);
    bnstats_part_k<<<dim3(512, 16), 256>>>(convR, 512, 64, part);
    bnht_pack_k<false, true, true><<<dim3(2, 16, NB), 256>>>(
        convR, out + O_L4R, nullptr, pH[0], pL[0], part, G[4], B[4], 512, 64, 3);

    // Layer 5: 512->512 @8, fused pool -> 4
    convmma_k<512, 8, false, true><<<dim3(128, 4), 128>>>(
        pb[0], nullptr, bwfB + FW5, nullptr, poolB, 512);
    convmma_k<512, 8, true, true><<<dim3(128, 4), 128>>>(
        pH[0], pL[0], bwfH + FW5, bwfL + FW5, poolR, 512);
    bnstats_part_k<<<dim3(512, 16), 256>>>(poolB, 512, 16, part);
    bnhtfin_k<<<(NB * 512 * 16) / 256, 256>>>(poolB, out + O_L5B, part, G[5], B[5]);
    bnstats_part_k<<<dim3(512, 16), 256>>>(poolR, 512, 16, part);
    bnhtfin_k<<<(NB * 512 * 16) / 256, 256>>>(poolR, out + O_L5R, part, G[5], B[5]);

    // penul + FC
    copy_k<<<(NB * 8192) / 256, 256>>>(out + O_L5B, out + O_PENUL);
    fc_k<<<NB, 256>>>(out + O_PENUL, fcw, fcb, out + O_OUT);
}

// round 17
// speedup vs baseline: 1.0383x; 1.0383x over previous
#include <cuda_runtime.h>
#include <cstddef>
#include <cstdint>

#define NB 128  // batch

// ---------------- output layout (tuple concat, fp32) ----------------
static const size_t O_OUT   = 0;
static const size_t O_PENUL = 1280;
static const size_t O_L1B   = 1049856;
static const size_t O_L1R   = 5244160;
static const size_t O_L2B   = 9438464;
static const size_t O_L2R   = 17827072;
static const size_t O_L3B   = 26215680;
static const size_t O_L3R   = 28312832;
static const size_t O_L4B   = 30409984;
static const size_t O_L4R   = 34604288;
static const size_t O_L5B   = 38798592;
static const size_t O_L5R   = 39847168;

// ---------------- scratch ----------------
#define PLSZ 18939904
__device__ float    g_convB[16777216];
__device__ float    g_convR[16777216];
__device__ float    g_poolB[4194304];
__device__ float    g_poolR[4194304];
__device__ uint16_t g_pbin[2][PLSZ];
__device__ uint16_t g_prealH[2][PLSZ];
__device__ uint16_t g_prealL[2][PLSZ];
__device__ uint4    g_bwfB[571392];
__device__ uint4    g_bwfH[571392];
__device__ uint4    g_bwfL[571392];
__device__ double   g_part[16384];      // BN partials: [C<=512][16][2]
__device__ float    g_mean[1024];
__device__ float    g_rstd[1024];

static const size_t FW1 = 0;
static const size_t FW2 = 18432;
static const size_t FW3 = 55296;
static const size_t FW4 = 129024;
static const size_t FW5 = 276480;

// ---------------- bf16 helpers ----------------
__device__ __forceinline__ uint16_t f2bf(float x) {
    uint16_t r; asm("cvt.rn.bf16.f32 %0, %1;" : "=h"(r) : "f"(x)); return r;
}
__device__ __forceinline__ float bf2f(uint16_t h) {
    return __uint_as_float(((uint32_t)h) << 16);
}

// ---------------- FUSED weight prep: sign -> fragments directly ----------------
template<int CIN>
__global__ void __launch_bounds__(256) wsignF_k(const float* __restrict__ w,
                                                uint4* __restrict__ frag) {
    constexpr int K = CIN * 9;
    constexpr int NCH = K / 16;
    __shared__ float rows[2][K];
    __shared__ double shd[256];
    int tid = threadIdx.x;
    int grp = blockIdx.x;
    int ocblk = grp >> 6;
    int w_ = (grp >> 4) & 3, mt = (grp >> 3) & 1, gid = grp & 7;
    int oc_lo = ocblk * 128 + w_ * 32 + mt * 16 + gid;
    const float* wlo = w + (size_t)oc_lo * K;
    const float* whi = w + (size_t)(oc_lo + 8) * K;
    for (int j = tid; j < K; j += 256) { rows[0][j] = wlo[j]; rows[1][j] = whi[j]; }
    __syncthreads();
    int half = tid >> 7, t = tid & 127;
    double s = 0.0;
    for (int j = t; j < K; j += 128) s += (double)rows[half][j];
    shd[tid] = s; __syncthreads();
    for (int st = 64; st > 0; st >>= 1) {
        if (t < st) shd[tid] += shd[tid + st];
        __syncthreads();
    }
    float m_lo = (float)(shd[0]   / (double)K);
    float m_hi = (float)(shd[128] / (double)K);
    auto sgn = [](float v, float m) -> uint32_t {
        float d = v - m;
        return (d > 0.f) ? 0x3F80u : ((d < 0.f) ? 0xBF80u : 0u);
    };
    auto src = [&](int h, int k) -> float {
        int cg = k / 576; int r = k % 576; int tap = r / 64; int cin = cg * 64 + (r % 64);
        return rows[h][cin * 9 + tap];
    };
    for (int e = tid; e < NCH * 4; e += 256) {
        int c = e >> 2, tig = e & 3;
        int k0 = c * 16 + tig * 2;
        uint4 v;
        v.x = sgn(src(0, k0), m_lo)     | (sgn(src(0, k0 + 1), m_lo) << 16);
        v.y = sgn(src(1, k0), m_hi)     | (sgn(src(1, k0 + 1), m_hi) << 16);
        v.z = sgn(src(0, k0 + 8), m_lo) | (sgn(src(0, k0 + 9), m_lo) << 16);
        v.w = sgn(src(1, k0 + 8), m_hi) | (sgn(src(1, k0 + 9), m_hi) << 16);
        frag[((size_t)(ocblk * NCH + c)) * 256 + w_ * 64 + mt * 32 + gid * 4 + tig] = v;
    }
}

// ---------------- FUSED weight prep: real hi/lo -> fragments directly ----------------
template<int CIN>
__global__ void __launch_bounds__(256) wrealF_k(const float* __restrict__ w,
                                                uint4* __restrict__ fragH,
                                                uint4* __restrict__ fragL) {
    constexpr int K = CIN * 9;
    constexpr int NCH = K / 16;
    __shared__ float rows[2][K];
    int tid = threadIdx.x;
    int grp = blockIdx.x;
    int ocblk = grp >> 6;
    int w_ = (grp >> 4) & 3, mt = (grp >> 3) & 1, gid = grp & 7;
    int oc_lo = ocblk * 128 + w_ * 32 + mt * 16 + gid;
    const float* wlo = w + (size_t)oc_lo * K;
    const float* whi = w + (size_t)(oc_lo + 8) * K;
    for (int j = tid; j < K; j += 256) { rows[0][j] = wlo[j]; rows[1][j] = whi[j]; }
    __syncthreads();
    auto src = [&](int h, int k) -> float {
        int cg = k / 576; int r = k % 576; int tap = r / 64; int cin = cg * 64 + (r % 64);
        return rows[h][cin * 9 + tap];
    };
    for (int e = tid; e < NCH * 4; e += 256) {
        int c = e >> 2, tig = e & 3;
        int k0 = c * 16 + tig * 2;
        float vals[8] = { src(0, k0), src(0, k0 + 1), src(1, k0), src(1, k0 + 1),
                          src(0, k0 + 8), src(0, k0 + 9), src(1, k0 + 8), src(1, k0 + 9) };
        uint16_t h8[8], l8[8];
#pragma unroll
        for (int q = 0; q < 8; q++) {
            h8[q] = f2bf(vals[q]);
            l8[q] = f2bf(vals[q] - bf2f(h8[q]));
        }
        size_t at = ((size_t)(ocblk * NCH + c)) * 256 + w_ * 64 + mt * 32 + gid * 4 + tig;
        uint4 vh, vl;
        vh.x = (uint32_t)h8[0] | ((uint32_t)h8[1] << 16);
        vh.y = (uint32_t)h8[2] | ((uint32_t)h8[3] << 16);
        vh.z = (uint32_t)h8[4] | ((uint32_t)h8[5] << 16);
        vh.w = (uint32_t)h8[6] | ((uint32_t)h8[7] << 16);
        vl.x = (uint32_t)l8[0] | ((uint32_t)l8[1] << 16);
        vl.y = (uint32_t)l8[2] | ((uint32_t)l8[3] << 16);
        vl.z = (uint32_t)l8[4] | ((uint32_t)l8[5] << 16);
        vl.w = (uint32_t)l8[6] | ((uint32_t)l8[7] << 16);
        fragH[at] = vh; fragL[at] = vl;
    }
}

// ---------------- border zero for padded planes ----------------
__global__ void border_k(uint16_t* __restrict__ a, uint16_t* __restrict__ b,
                         int H, int W, int C) {
    int S = 2 * (W + 2) * C + 2 * H * C;
    size_t i = (size_t)blockIdx.x * 256 + threadIdx.x;
    int n = (int)(i / S);
    if (n >= NB) return;
    int r = (int)(i % S);
    int T = (W + 2) * C;
    int prow, pcol, c;
    if (r < T)            { prow = 0;     pcol = r / C;          c = r % C; }
    else if (r < 2 * T)   { int r2 = r - T; prow = H + 1; pcol = r2 / C; c = r2 % C; }
    else {
        int r3 = r - 2 * T;
        if (r3 < H * C)   { prow = 1 + r3 / C; pcol = 0;     c = r3 % C; }
        else              { int r4 = r3 - H * C; prow = 1 + r4 / C; pcol = W + 1; c = r4 % C; }
    }
    size_t at = (((size_t)n * (H + 2) + prow) * (W + 2) + pcol) * C + c;
    a[at] = 0;
    if (b) b[at] = 0;
}

// ---------------- FUSED: conv0 + w1 sign frags + w1 real frags + L1 borders ----------------
__global__ void __launch_bounds__(256) conv0wsign_k(const float* __restrict__ x,
                                                    const float* __restrict__ w0,
                                                    float* __restrict__ out,
                                                    const float* __restrict__ w1,
                                                    uint4* __restrict__ wfragB,
                                                    uint4* __restrict__ wfragH,
                                                    uint4* __restrict__ wfragL,
                                                    uint16_t* __restrict__ pb0,
                                                    uint16_t* __restrict__ pH0,
                                                    uint16_t* __restrict__ pL0) {
    __shared__ float As[9][64];
    __shared__ float Bs[10][10];
    __shared__ double shd[256];
    __shared__ float wrows[2][1152];
    int tid = threadIdx.x;

    if (blockIdx.x >= 12608) {
        // w1 real fragments (CIN=128, K=1152, NCH=72)
        int grp = blockIdx.x - 12608;
        int w_ = (grp >> 4) & 3, mt = (grp >> 3) & 1, gid = grp & 7;
        int oc_lo = w_ * 32 + mt * 16 + gid;
        const int K = 1152, NCH = 72;
        const float* wlo = w1 + (size_t)oc_lo * K;
        const float* whi = w1 + (size_t)(oc_lo + 8) * K;
        for (int j = tid; j < K; j += 256) { wrows[0][j] = wlo[j]; wrows[1][j] = whi[j]; }
        __syncthreads();
        auto src = [&](int h, int k) -> float {
            int cg = k / 576; int r = k % 576; int tap = r / 64; int cin = cg * 64 + (r % 64);
            return wrows[h][cin * 9 + tap];
        };
        for (int e = tid; e < NCH * 4; e += 256) {
            int c = e >> 2, tig = e & 3;
            int k0 = c * 16 + tig * 2;
            float vals[8] = { src(0, k0), src(0, k0 + 1), src(1, k0), src(1, k0 + 1),
                              src(0, k0 + 8), src(0, k0 + 9), src(1, k0 + 8), src(1, k0 + 9) };
            uint16_t h8[8], l8[8];
#pragma unroll
            for (int q = 0; q < 8; q++) {
                h8[q] = f2bf(vals[q]);
                l8[q] = f2bf(vals[q] - bf2f(h8[q]));
            }
            size_t at = ((size_t)c) * 256 + w_ * 64 + mt * 32 + gid * 4 + tig;
            uint4 vh, vl;
            vh.x = (uint32_t)h8[0] | ((uint32_t)h8[1] << 16);
            vh.y = (uint32_t)h8[2] | ((uint32_t)h8[3] << 16);
            vh.z = (uint32_t)h8[4] | ((uint32_t)h8[5] << 16);
            vh.w = (uint32_t)h8[6] | ((uint32_t)h8[7] << 16);
            vl.x = (uint32_t)l8[0] | ((uint32_t)l8[1] << 16);
            vl.y = (uint32_t)l8[2] | ((uint32_t)l8[3] << 16);
            vl.z = (uint32_t)l8[4] | ((uint32_t)l8[5] << 16);
            vl.w = (uint32_t)l8[6] | ((uint32_t)l8[7] << 16);
            wfragH[at] = vh; wfragL[at] = vl;
        }
        return;
    }

    if (blockIdx.x >= 4160) {
        const int H = 32, W = 32, C = 128;
        const int T = (W + 2) * C;
        const int S = 2 * T + 2 * H * C;
        size_t i = (size_t)(blockIdx.x - 4160) * 256 + tid;
        int n = (int)(i / S);
        if (n >= NB) return;
        int r = (int)(i % S);
        int prow, pcol, c;
        if (r < T)          { prow = 0;  pcol = r / C; c = r % C; }
        else if (r < 2 * T) { int r2 = r - T; prow = H + 1; pcol = r2 / C; c = r2 % C; }
        else {
            int r3 = r - 2 * T;
            if (r3 < H * C) { prow = 1 + r3 / C; pcol = 0; c = r3 % C; }
            else            { int r4 = r3 - H * C; prow = 1 + r4 / C; pcol = W + 1; c = r4 % C; }
        }
        size_t at = (((size_t)n * (H + 2) + prow) * (W + 2) + pcol) * C + c;
        pb0[at] = 0; pH0[at] = 0; pL0[at] = 0;
        return;
    }

    if (blockIdx.x >= 4096) {
        int grp = blockIdx.x - 4096;
        int w_  = (grp >> 4) & 3;
        int mt  = (grp >> 3) & 1;
        int gid = grp & 7;
        int oc_lo = w_ * 32 + mt * 16 + gid;
        int oc_hi = oc_lo + 8;
        const int K = 1152;
        int half = tid >> 7;
        int t    = tid & 127;
        const float* wp = w1 + (size_t)(half ? oc_hi : oc_lo) * K;
        double s = 0.0;
        for (int i = t; i < K; i += 128) s += (double)wp[i];
        shd[tid] = s; __syncthreads();
        for (int st = 64; st > 0; st >>= 1) {
            if (t < st) shd[tid] += shd[tid + st];
            __syncthreads();
        }
        float m_lo = (float)(shd[0]   / (double)K);
        float m_hi = (float)(shd[128] / (double)K);
        const float* wlo = w1 + (size_t)oc_lo * K;
        const float* whi = w1 + (size_t)oc_hi * K;
        auto sgn = [](float v, float m) -> uint32_t {
            float d = v - m;
            return (d > 0.f) ? 0x3F80u : ((d < 0.f) ? 0xBF80u : 0u);
        };
        auto src = [](const float* p, int k) -> float {
            int cg = k / 576; int r = k % 576; int tap = r / 64; int cin = cg * 64 + (r % 64);
            return p[cin * 9 + tap];
        };
        for (int e = tid; e < 72 * 4; e += 256) {
            int c = e >> 2, tig = e & 3;
            int k0 = c * 16 + tig * 2;
            uint4 v;
            v.x = sgn(src(wlo, k0), m_lo)     | (sgn(src(wlo, k0 + 1), m_lo) << 16);
            v.y = sgn(src(whi, k0), m_hi)     | (sgn(src(whi, k0 + 1), m_hi) << 16);
            v.z = sgn(src(wlo, k0 + 8), m_lo) | (sgn(src(wlo, k0 + 9), m_lo) << 16);
            v.w = sgn(src(whi, k0 + 8), m_hi) | (sgn(src(whi, k0 + 9), m_hi) << 16);
            wfragB[((size_t)c * 4 + w_) * 64 + mt * 32 + gid * 4 + tig] = v;
        }
        return;
    }

    // conv0
    const int CIN = 3, HH = 32, Cout = 128;
    int bx = blockIdx.x;
    int tile = bx & 15;
    int ty0 = (tile / 4) * 8;
    int tx0 = (tile % 4) * 8;
    int oc0 = ((bx >> 4) & 1) * 64;
    int n   = bx >> 5;
    int pos_t = tid & 15;
    int oc_t  = tid >> 4;

    float acc[4][4];
#pragma unroll
    for (int j = 0; j < 4; j++)
#pragma unroll
        for (int i = 0; i < 4; i++) acc[j][i] = 0.f;

    const float* inN = x + (size_t)n * CIN * HH * HH;

    for (int cin = 0; cin < CIN; cin++) {
        for (int idx = tid; idx < 576; idx += 256) {
            int oc = idx / 9, tap = idx % 9;
            As[tap][oc] = w0[(((size_t)(oc0 + oc)) * CIN + cin) * 9 + tap];
        }
        if (tid < 100) {
            int r = tid / 10, c = tid % 10;
            int gy = ty0 + r - 1, gx = tx0 + c - 1;
            float v = 0.f;
            if (gy >= 0 && gy < HH && gx >= 0 && gx < HH)
                v = inN[(size_t)cin * HH * HH + gy * HH + gx];
            Bs[r][c] = v;
        }
        __syncthreads();
#pragma unroll
        for (int tap = 0; tap < 9; tap++) {
            int dy = tap / 3, dx = tap % 3;
            float4 wv = *(const float4*)&As[tap][oc_t * 4];
#pragma unroll
            for (int j = 0; j < 4; j++) {
                int p = pos_t + 16 * j;
                float bv = Bs[(p >> 3) + dy][(p & 7) + dx];
                acc[j][0] += bv * wv.x;
                acc[j][1] += bv * wv.y;
                acc[j][2] += bv * wv.z;
                acc[j][3] += bv * wv.w;
            }
        }
        __syncthreads();
    }

#pragma unroll
    for (int j = 0; j < 4; j++) {
        int p = pos_t + 16 * j;
        int oy = ty0 + (p >> 3), ox = tx0 + (p & 7);
#pragma unroll
        for (int i = 0; i < 4; i++) {
            int oc = oc0 + oc_t * 4 + i;
            out[(((size_t)n * Cout + oc) * HH + oy) * HH + ox] = acc[j][i];
        }
    }
}

// ---------------- bf16 MMA + ldmatrix ----------------
__device__ __forceinline__ void mma_bf16(float* d, const uint32_t* a, const uint32_t* b) {
    asm volatile(
        "mma.sync.aligned.m16n8k16.row.col.f32.bf16.bf16.f32 "
        "{%0,%1,%2,%3}, {%4,%5,%6,%7}, {%8,%9}, {%0,%1,%2,%3};\n"
        : "+f"(d[0]), "+f"(d[1]), "+f"(d[2]), "+f"(d[3])
        : "r"(a[0]), "r"(a[1]), "r"(a[2]), "r"(a[3]),
          "r"(b[0]), "r"(b[1]));
}
__device__ __forceinline__ void ldsm_x4(uint32_t& r0, uint32_t& r1, uint32_t& r2, uint32_t& r3,
                                        uint32_t addr) {
    asm volatile("ldmatrix.sync.aligned.m8n8.x4.shared.b16 {%0,%1,%2,%3}, [%4];"
                 : "=r"(r0), "=r"(r1), "=r"(r2), "=r"(r3) : "r"(addr));
}

// ---------------- implicit-GEMM conv v8 (UNCHANGED) ----------------
template<int CIN, int H, bool SPLIT, bool POOL>
__global__ void __launch_bounds__(128) convmma_k(const uint16_t* __restrict__ inH,
                                                 const uint16_t* __restrict__ inL,
                                                 const uint4* __restrict__ wfH,
                                                 const uint4* __restrict__ wfL,
                                                 float* __restrict__ out,
                                                 int Cout) {
    constexpr int Wd = H;
    constexpr int HW = H * H;
    constexpr int K  = CIN * 9;
    constexpr int NCH = K / 16;
    constexpr int LGHW = (HW == 1024) ? 10 : (HW == 256) ? 8 : 6;
    constexpr int LGW  = (H == 32) ? 5 : (H == 16) ? 4 : 3;
    constexpr int NS = SPLIT ? 2 : 1;
    constexpr int NROWS = 64 / Wd;
    constexpr int PADP  = (NROWS + 2) * (Wd + 2);
    constexpr int NGRP  = CIN / 64;

    __shared__ __align__(16) uint16_t Ts[NS][PADP * 72];

    int tid  = threadIdx.x;
    int lane = tid & 31;
    int warp = tid >> 5;
    int gid  = lane >> 2;
    int tig  = lane & 3;

    int col0 = blockIdx.x * 64;
    int oc0  = blockIdx.y * 128;
    int nimg = col0 >> LGHW;
    int y0   = (col0 & (HW - 1)) >> LGW;
    size_t gtile = (((size_t)nimg * (H + 2) + y0) * (Wd + 2)) * CIN;

    size_t abase = (size_t)(oc0 >> 7) * NCH * 256 + (size_t)warp * 64 + lane;

    int posb[4];
    {
        int sub = ((lane >> 4) & 1) * 8 + (lane & 7);
        int kh  = (lane >> 3) & 1;
#pragma unroll
        for (int p = 0; p < 4; p++) {
            int bp = p * 16 + sub;
            int ry = bp >> LGW;
            int xx = bp & (Wd - 1);
            posb[p] = ((ry + 1) * (Wd + 2) + xx + 1) * 144 + kh * 16;
        }
    }
    uint32_t tb[NS];
#pragma unroll
    for (int s = 0; s < NS; s++)
        tb[s] = (uint32_t)__cvta_generic_to_shared(&Ts[s][0]);

    float acc[2][8][4];
#pragma unroll
    for (int mt = 0; mt < 2; mt++)
#pragma unroll
        for (int nt = 0; nt < 8; nt++)
#pragma unroll
            for (int r = 0; r < 4; r++) acc[mt][nt][r] = 0.f;

    uint4 acurH[2], acurL[2], anxtH[2], anxtL[2];
    auto load_A = [&](int c, uint4* aH, uint4* aL) {
#pragma unroll
        for (int mt = 0; mt < 2; mt++) {
            aH[mt] = wfH[abase + (size_t)c * 256 + mt * 32];
            if (SPLIT) aL[mt] = wfL[abase + (size_t)c * 256 + mt * 32];
        }
    };

    load_A(0, acurH, acurL);
    int c = 0;

    for (int cg = 0; cg < NGRP; cg++) {
        for (int it = tid; it < PADP * 8; it += 128) {
            int row = it >> 3, o = it & 7;
            size_t gsrc = gtile + (size_t)row * CIN + cg * 64 + o * 8;
            *(uint4*)&Ts[0][row * 72 + o * 8] = *(const uint4*)(inH + gsrc);
            if (SPLIT)
                *(uint4*)&Ts[1][row * 72 + o * 8] = *(const uint4*)(inL + gsrc);
        }
        __syncthreads();

#pragma unroll 1
        for (int tap = 0; tap < 9; tap++) {
            int to = ((tap / 3 - 1) * (Wd + 2) + (tap % 3 - 1)) * 144;
#pragma unroll
            for (int j = 0; j < 4; j++) {
                bool more = (c + 1 < NCH);
                if (more) load_A(c + 1, anxtH, anxtL);

                uint32_t bf[NS][8][2];
#pragma unroll
                for (int s = 0; s < NS; s++)
#pragma unroll
                    for (int p = 0; p < 4; p++)
                        ldsm_x4(bf[s][2 * p][0], bf[s][2 * p][1],
                                bf[s][2 * p + 1][0], bf[s][2 * p + 1][1],
                                tb[s] + (uint32_t)(posb[p] + to + j * 32));
#pragma unroll
                for (int mt = 0; mt < 2; mt++)
#pragma unroll
                    for (int nt = 0; nt < 8; nt++) {
                        if (SPLIT) {
                            mma_bf16(acc[mt][nt], (const uint32_t*)&acurL[mt], bf[0][nt]);
                            mma_bf16(acc[mt][nt], (const uint32_t*)&acurH[mt], bf[1][nt]);
                        }
                        mma_bf16(acc[mt][nt], (const uint32_t*)&acurH[mt], bf[0][nt]);
                    }
                if (more) {
                    acurH[0] = anxtH[0]; acurH[1] = anxtH[1];
                    if (SPLIT) { acurL[0] = anxtL[0]; acurL[1] = anxtL[1]; }
                }
                c++;
            }
        }
        __syncthreads();
    }

    if (!POOL) {
#pragma unroll
        for (int mt = 0; mt < 2; mt++) {
#pragma unroll
            for (int nt = 0; nt < 8; nt++) {
                int cc = col0 + nt * 8 + 2 * tig;
                int n_ = cc >> LGHW;
                int pp = cc & (HW - 1);
#pragma unroll
                for (int h = 0; h < 2; h++) {
                    int m = oc0 + warp * 32 + mt * 16 + gid + 8 * h;
                    float2 v = make_float2(acc[mt][nt][2 * h], acc[mt][nt][2 * h + 1]);
                    *(float2*)&out[((size_t)n_ * Cout + m) * HW + pp] = v;
                }
            }
        }
    } else {
        constexpr int PST = H / 8;
        constexpr int HO = H / 2;
#pragma unroll
        for (int mt = 0; mt < 2; mt++) {
#pragma unroll
            for (int nt = 0; nt < 8; nt++) {
                if (((nt / PST) & 1) != 0) continue;
                int np = nt + PST;
                int cc = col0 + nt * 8 + 2 * tig;
                int n_ = cc >> LGHW;
                int pos_ = cc & (HW - 1);
                int oy = (pos_ >> LGW) >> 1;
                int ox = (pos_ & (Wd - 1)) >> 1;
#pragma unroll
                for (int h = 0; h < 2; h++) {
                    int m = oc0 + warp * 32 + mt * 16 + gid + 8 * h;
                    float v = fmaxf(fmaxf(acc[mt][nt][2 * h], acc[mt][nt][2 * h + 1]),
                                    fmaxf(acc[mt][np][2 * h], acc[mt][np][2 * h + 1]));
                    out[((size_t)n_ * Cout + m) * (HO * HO) + oy * HO + ox] = v;
                }
            }
        }
    }
}

// ---------------- BN partial sums (deterministic, 16-way) ----------------
__global__ void bnstats_part_k(const float* __restrict__ x, int C, int HW,
                               double* __restrict__ part) {
    int c = blockIdx.x;
    int s = blockIdx.y;
    int tid = threadIdx.x;
    double s1 = 0.0, s2 = 0.0;
    for (int n = s * 8; n < s * 8 + 8; n++) {
        const float* xp = x + ((size_t)n * C + c) * HW;
        for (int p = tid; p < HW; p += 256) {
            float v = xp[p];
            s1 += (double)v;
            s2 += (double)v * (double)v;
        }
    }
    __shared__ double sh1[256], sh2[256];
    sh1[tid] = s1; sh2[tid] = s2; __syncthreads();
    for (int st = 128; st > 0; st >>= 1) {
        if (tid < st) { sh1[tid] += sh1[tid + st]; sh2[tid] += sh2[tid + st]; }
        __syncthreads();
    }
    if (tid == 0) {
        part[((size_t)c * 16 + s) * 2 + 0] = sh1[0];
        part[((size_t)c * 16 + s) * 2 + 1] = sh2[0];
    }
}

__global__ void bnstats_fin_k(const double* __restrict__ part, int C, int HW,
                              float* __restrict__ mean, float* __restrict__ rstd) {
    int c = blockIdx.x * 256 + threadIdx.x;
    if (c >= C) return;
    double s1 = 0.0, s2 = 0.0;
#pragma unroll
    for (int s = 0; s < 16; s++) {
        s1 += part[((size_t)c * 16 + s) * 2 + 0];
        s2 += part[((size_t)c * 16 + s) * 2 + 1];
    }
    double M = (double)NB * HW;
    double m = s1 / M;
    double var = s2 / M - m * m;
    mean[c] = (float)m;
    rstd[c] = (float)(1.0 / sqrt(var + 1e-5));
}

// ---------------- BN apply + hardtanh + padded plane pack ----------------
template<bool BIN, bool REALP, bool WF32>
__global__ void bnht_pack_k(const float* __restrict__ x, float* __restrict__ y32,
                            uint16_t* __restrict__ pbin,
                            uint16_t* __restrict__ pH, uint16_t* __restrict__ pL,
                            const float* __restrict__ mean, const float* __restrict__ rstd,
                            const float* __restrict__ g, const float* __restrict__ bb,
                            int C, int HW, int lgW) {
    __shared__ float ts[32][33];
    int tx = threadIdx.x & 31, ty = threadIdx.x >> 5;
    int p0 = blockIdx.x * 32, c0 = blockIdx.y * 32, n = blockIdx.z;
    int W = 1 << lgW;
    int H = HW >> lgW;
#pragma unroll
    for (int r = 0; r < 4; r++) {
        int c = c0 + ty + r * 8;
        size_t idx = ((size_t)n * C + c) * HW + p0 + tx;
        float v = x[idx];
        v = (v - mean[c]) * rstd[c] * g[c] + bb[c];
        v = fminf(1.f, fmaxf(-1.f, v));
        if (WF32) y32[idx] = v;
        ts[ty + r * 8][tx] = v;
    }
    __syncthreads();
#pragma unroll
    for (int r = 0; r < 4; r++) {
        int p = p0 + ty + r * 8;
        int c = c0 + tx;
        float v = ts[tx][ty + r * 8];
        int py = p >> lgW, px = p & (W - 1);
        size_t a = (((size_t)n * (H + 2) + py + 1) * (W + 2) + px + 1) * C + c;
        if (BIN)
            pbin[a] = (v > 0.f) ? 0x3F80 : ((v < 0.f) ? 0xBF80 : 0);
        if (REALP) {
            uint16_t hi = f2bf(v);
            float lo = v - bf2f(hi);
            pH[a] = hi;
            pL[a] = f2bf(lo);
        }
    }
}

// ---------------- plain BN apply + hardtanh (L5 outputs) ----------------
__global__ void bnht_k(const float* __restrict__ x, float* __restrict__ y,
                       const float* __restrict__ mean, const float* __restrict__ rstd,
                       const float* __restrict__ g, const float* __restrict__ bb,
                       int lgHW, int Cmask) {
    size_t i = (size_t)blockIdx.x * 256 + threadIdx.x;
    int c = (int)((i >> lgHW) & (size_t)Cmask);
    float v = (x[i] - mean[c]) * rstd[c] * g[c] + bb[c];
    y[i] = fminf(1.f, fmaxf(-1.f, v));
}

// ---------------- copy ----------------
__global__ void copy_k(const float* __restrict__ src, float* __restrict__ dst) {
    size_t i = (size_t)blockIdx.x * 256 + threadIdx.x;
    dst[i] = src[i];
}

// ---------------- FC ----------------
__global__ void fc_k(const float* __restrict__ p, const float* __restrict__ w,
                     const float* __restrict__ b, float* __restrict__ out) {
    int n = blockIdx.x;
    int tid = threadIdx.x;
    float acc[10];
#pragma unroll
    for (int j = 0; j < 10; j++) acc[j] = 0.f;
    const float* pn = p + (size_t)n * 8192;
    for (int k = tid; k < 8192; k += 256) {
        float pv = pn[k];
#pragma unroll
        for (int j = 0; j < 10; j++) acc[j] += pv * w[(size_t)j * 8192 + k];
    }
    __shared__ float sh[256];
    for (int j = 0; j < 10; j++) {
        sh[tid] = acc[j]; __syncthreads();
        for (int st = 128; st > 0; st >>= 1) {
            if (tid < st) sh[tid] += sh[tid + st];
            __syncthreads();
        }
        if (tid == 0) out[n * 10 + j] = sh[0] + b[j];
        __syncthreads();
    }
}

// ---------------- host launch ----------------
extern "C" void kernel_launch(void* const* d_in, const int* in_sizes, int n_in,
                              void* d_out, int out_size) {
    (void)in_sizes; (void)n_in; (void)out_size;
    const float* x   = (const float*)d_in[0];
    const float* w0  = (const float*)d_in[1];
    const float* w1  = (const float*)d_in[2];
    const float* w2  = (const float*)d_in[3];
    const float* w3  = (const float*)d_in[4];
    const float* w4  = (const float*)d_in[5];
    const float* w5  = (const float*)d_in[6];
    const float* fcw = (const float*)d_in[7];
    const float* fcb = (const float*)d_in[8];
    const float* G[6], *B[6];
    for (int i = 0; i < 6; i++) { G[i] = (const float*)d_in[9 + 2*i]; B[i] = (const float*)d_in[10 + 2*i]; }
    float* out = (float*)d_out;

    float *convB, *convR, *poolB, *poolR, *mean, *rstd;
    double *part;
    uint16_t *pbin, *prH, *prL;
    uint4 *bwfB, *bwfH, *bwfL;
    cudaGetSymbolAddress((void**)&convB, g_convB);
    cudaGetSymbolAddress((void**)&convR, g_convR);
    cudaGetSymbolAddress((void**)&poolB, g_poolB);
    cudaGetSymbolAddress((void**)&poolR, g_poolR);
    cudaGetSymbolAddress((void**)&pbin,  g_pbin);
    cudaGetSymbolAddress((void**)&prH,   g_prealH);
    cudaGetSymbolAddress((void**)&prL,   g_prealL);
    cudaGetSymbolAddress((void**)&bwfB,  g_bwfB);
    cudaGetSymbolAddress((void**)&bwfH,  g_bwfH);
    cudaGetSymbolAddress((void**)&bwfL,  g_bwfL);
    cudaGetSymbolAddress((void**)&part,  g_part);
    cudaGetSymbolAddress((void**)&mean,  g_mean);
    cudaGetSymbolAddress((void**)&rstd,  g_rstd);
    uint16_t* pb[2]  = { pbin, pbin + PLSZ };
    uint16_t* pH[2]  = { prH,  prH  + PLSZ };
    uint16_t* pL[2]  = { prL,  prL  + PLSZ };

    // 0: conv0 + w1 sign frags + w1 real frags + L1 borders
    conv0wsign_k<<<12672, 256>>>(x, w0, convB, w1, bwfB + FW1, bwfH + FW1, bwfL + FW1,
                                 pb[0], pH[0], pL[0]);
    bnstats_part_k<<<dim3(128, 16), 256>>>(convB, 128, 1024, part);
    bnstats_fin_k<<<1, 256>>>(part, 128, 1024, mean, rstd);
    bnht_pack_k<true, true, false><<<dim3(32, 4, NB), 256>>>(     // index 3 <- profiled
        convB, nullptr, pb[0], pH[0], pL[0], mean, rstd, G[0], B[0], 128, 1024, 5);

    // Layer 1: 128->128 @32, fused pool -> 16
    convmma_k<128, 32, true, true><<<dim3(2048, 1), 128>>>(
        pH[0], pL[0], bwfH + FW1, bwfL + FW1, poolR, 128);
    convmma_k<128, 32, false, true><<<dim3(2048, 1), 128>>>(
        pb[0], nullptr, bwfB + FW1, nullptr, poolB, 128);

    // weight prep for layers 2..5 (fused single-pass)
    wsignF_k<128><<<128, 256>>>(w2, bwfB + FW2);
    wrealF_k<128><<<128, 256>>>(w2, bwfH + FW2, bwfL + FW2);
    wsignF_k<256><<<128, 256>>>(w3, bwfB + FW3);
    wrealF_k<256><<<128, 256>>>(w3, bwfH + FW3, bwfL + FW3);
    wsignF_k<256><<<256, 256>>>(w4, bwfB + FW4);
    wrealF_k<256><<<256, 256>>>(w4, bwfH + FW4, bwfL + FW4);
    wsignF_k<512><<<256, 256>>>(w5, bwfB + FW5);
    wrealF_k<512><<<256, 256>>>(w5, bwfH + FW5, bwfL + FW5);

    // borders for L2-input planes (16,16,128)
    border_k<<<4353, 256>>>(pb[1], nullptr, 16, 16, 128);
    border_k<<<4353, 256>>>(pH[1], pL[1], 16, 16, 128);

    bnstats_part_k<<<dim3(128, 16), 256>>>(poolB, 128, 256, part);
    bnstats_fin_k<<<1, 256>>>(part, 128, 256, mean, rstd);
    bnht_pack_k<true, false, true><<<dim3(8, 4, NB), 256>>>(
        poolB, out + O_L1B, pb[1], nullptr, nullptr, mean, rstd, G[1], B[1], 128, 256, 4);
    bnstats_part_k<<<dim3(128, 16), 256>>>(poolR, 128, 256, part);
    bnstats_fin_k<<<1, 256>>>(part, 128, 256, mean + 512, rstd + 512);
    bnht_pack_k<false, true, true><<<dim3(8, 4, NB), 256>>>(
        poolR, out + O_L1R, nullptr, pH[1], pL[1], mean + 512, rstd + 512, G[1], B[1], 128, 256, 4);

    // Layer 2: 128->256 @16, no pool
    convmma_k<128, 16, false, false><<<dim3(512, 2), 128>>>(
        pb[1], nullptr, bwfB + FW2, nullptr, convB, 256);
    convmma_k<128, 16, true, false><<<dim3(512, 2), 128>>>(
        pH[1], pL[1], bwfH + FW2, bwfL + FW2, convR, 256);
    border_k<<<8704, 256>>>(pb[0], nullptr, 16, 16, 256);
    border_k<<<8704, 256>>>(pH[0], pL[0], 16, 16, 256);
    bnstats_part_k<<<dim3(256, 16), 256>>>(convB, 256, 256, part);
    bnstats_fin_k<<<1, 256>>>(part, 256, 256, mean, rstd);
    bnht_pack_k<true, false, true><<<dim3(8, 8, NB), 256>>>(
        convB, out + O_L2B, pb[0], nullptr, nullptr, mean, rstd, G[2], B[2], 256, 256, 4);
    bnstats_part_k<<<dim3(256, 16), 256>>>(convR, 256, 256, part);
    bnstats_fin_k<<<1, 256>>>(part, 256, 256, mean + 512, rstd + 512);
    bnht_pack_k<false, true, true><<<dim3(8, 8, NB), 256>>>(
        convR, out + O_L2R, nullptr, pH[0], pL[0], mean + 512, rstd + 512, G[2], B[2], 256, 256, 4);

    // Layer 3: 256->256 @16, fused pool -> 8
    convmma_k<256, 16, false, true><<<dim3(512, 2), 128>>>(
        pb[0], nullptr, bwfB + FW3, nullptr, poolB, 256);
    convmma_k<256, 16, true, true><<<dim3(512, 2), 128>>>(
        pH[0], pL[0], bwfH + FW3, bwfL + FW3, poolR, 256);
    border_k<<<4608, 256>>>(pb[1], nullptr, 8, 8, 256);
    border_k<<<4608, 256>>>(pH[1], pL[1], 8, 8, 256);
    bnstats_part_k<<<dim3(256, 16), 256>>>(poolB, 256, 64, part);
    bnstats_fin_k<<<1, 256>>>(part, 256, 64, mean, rstd);
    bnht_pack_k<true, false, true><<<dim3(2, 8, NB), 256>>>(
        poolB, out + O_L3B, pb[1], nullptr, nullptr, mean, rstd, G[3], B[3], 256, 64, 3);
    bnstats_part_k<<<dim3(256, 16), 256>>>(poolR, 256, 64, part);
    bnstats_fin_k<<<1, 256>>>(part, 256, 64, mean + 512, rstd + 512);
    bnht_pack_k<false, true, true><<<dim3(2, 8, NB), 256>>>(
        poolR, out + O_L3R, nullptr, pH[1], pL[1], mean + 512, rstd + 512, G[3], B[3], 256, 64, 3);

    // Layer 4: 256->512 @8, no pool
    convmma_k<256, 8, false, false><<<dim3(128, 4), 128>>>(
        pb[1], nullptr, bwfB + FW4, nullptr, convB, 512);
    convmma_k<256, 8, true, false><<<dim3(128, 4), 128>>>(
        pH[1], pL[1], bwfH + FW4, bwfL + FW4, convR, 512);
    border_k<<<9216, 256>>>(pb[0], nullptr, 8, 8, 512);
    border_k<<<9216, 256>>>(pH[0], pL[0], 8, 8, 512);
    bnstats_part_k<<<dim3(512, 16), 256>>>(convB, 512, 64, part);
    bnstats_fin_k<<<2, 256>>>(part, 512, 64, mean, rstd);
    bnht_pack_k<true, false, true><<<dim3(2, 16, NB), 256>>>(
        convB, out + O_L4B, pb[0], nullptr, nullptr, mean, rstd, G[4], B[4], 512, 64, 3);
    bnstats_part_k<<<dim3(512, 16), 256>>>(convR, 512, 64, part);
    bnstats_fin_k<<<2, 256>>>(part, 512, 64, mean + 512, rstd + 512);
    bnht_pack_k<false, true, true><<<dim3(2, 16, NB), 256>>>(
        convR, out + O_L4R, nullptr, pH[0], pL[0], mean + 512, rstd + 512, G[4], B[4], 512, 64, 3);

    // Layer 5: 512->512 @8, fused pool -> 4
    convmma_k<512, 8, false, true><<<dim3(128, 4), 128>>>(
        pb[0], nullptr, bwfB + FW5, nullptr, poolB, 512);
    convmma_k<512, 8, true, true><<<dim3(128, 4), 128>>>(
        pH[0], pL[0], bwfH + FW5, bwfL + FW5, poolR, 512);
    bnstats_part_k<<<dim3(512, 16), 256>>>(poolB, 512, 16, part);
    bnstats_fin_k<<<2, 256>>>(part, 512, 16, mean, rstd);
    bnht_k<<<(NB * 512 * 16) / 256, 256>>>(poolB, out + O_L5B, mean, rstd, G[5], B[5], 4, 511);
    bnstats_part_k<<<dim3(512, 16), 256>>>(poolR, 512, 16, part);
    bnstats_fin_k<<<2, 256>>>(part, 512, 16, mean + 512, rstd + 512);
    bnht_k<<<(NB * 512 * 16) / 256, 256>>>(poolR, out + O_L5R, mean + 512, rstd + 512, G[5], B[5], 4, 511);

    // penul + FC
    copy_k<<<(NB * 8192) / 256, 256>>>(out + O_L5B, out + O_PENUL);
    fc_k<<<NB, 256>>>(out + O_PENUL, fcw, fcb, out + O_OUT);
}